// round 2
// baseline (speedup 1.0000x reference)
#include <cuda_runtime.h>
#include <cuda_bf16.h>
#include <cstdint>
#include <cstddef>

// ---------------------------------------------------------------------------
// Problem shapes (fixed)
// B=512, LATENT=256, LOCAL=256, HIDDEN=512, H=W=16 -> HW=256
// out[k][i][j] = sum_c pred[i][c] * positive[j][c][k]  - rowmax_j
// ---------------------------------------------------------------------------

#define BSZ     512
#define LATENT  256
#define LOCAL   256
#define HIDDEN  512
#define HW      256

// Scratch (static device allocations are allowed; cudaMalloc is not)
__device__ float g_h[BSZ * HIDDEN];                       // hidden activations
__device__ float g_a[BSZ * LATENT];                       // residual MLP out
__device__ float g_pred[BSZ * LOCAL];                     // pred = a @ Wc
__device__ float g_posT[(size_t)HW * BSZ * LOCAL];        // posT[k][j][c], 128 MB

// ---------------------------------------------------------------------------
// f32x2 packed helpers (Blackwell sm_103a)
// ---------------------------------------------------------------------------
__device__ __forceinline__ unsigned long long bc2(float x) {
    unsigned long long r;
    unsigned u = __float_as_uint(x);
    asm("mov.b64 %0, {%1, %1};" : "=l"(r) : "r"(u));
    return r;
}
__device__ __forceinline__ void fma2(unsigned long long& d,
                                     unsigned long long a,
                                     unsigned long long b) {
    asm("fma.rn.f32x2 %0, %1, %2, %0;" : "+l"(d) : "l"(a), "l"(b));
}
__device__ __forceinline__ float2 up2(unsigned long long v) {
    float2 f;
    asm("mov.b64 {%0, %1}, %2;" : "=f"(f.x), "=f"(f.y) : "l"(v));
    return f;
}

// ---------------------------------------------------------------------------
// Generic small fp32 GEMM: C[M,N] = act(A[M,K] @ B[K,N] + bias + res)
// 64x64 tile, 256 threads, 4x4 microtile, K-step 16.
// ---------------------------------------------------------------------------
__global__ void __launch_bounds__(256)
gemm_tile(const float* __restrict__ A, const float* __restrict__ B,
          const float* __restrict__ bias, const float* __restrict__ res,
          float* __restrict__ C, int M, int N, int K, int doRelu)
{
    __shared__ float As[16][64];   // [k][m]  (transposed on store)
    __shared__ float Bs[16][64];   // [k][n]

    const int tid = threadIdx.x;
    const int tig = tid >> 4;      // 0..15 -> i rows tig*4..+3
    const int tjg = tid & 15;      // 0..15 -> j cols tjg*4..+3
    const int m0  = blockIdx.y * 64;
    const int n0  = blockIdx.x * 64;

    const int arow = tid >> 2, aq = tid & 3;    // A tile: 64 rows x 4 quads
    const int brow = tid >> 4, bq = tid & 15;   // B tile: 16 rows x 16 quads

    float acc[4][4] = {};

    for (int kk = 0; kk < K; kk += 16) {
        float4 av = *(const float4*)(A + (size_t)(m0 + arow) * K + kk + aq * 4);
        float4 bv = *(const float4*)(B + (size_t)(kk + brow) * N + n0 + bq * 4);
        __syncthreads();
        As[aq * 4 + 0][arow] = av.x;
        As[aq * 4 + 1][arow] = av.y;
        As[aq * 4 + 2][arow] = av.z;
        As[aq * 4 + 3][arow] = av.w;
        *(float4*)&Bs[brow][bq * 4] = bv;
        __syncthreads();
#pragma unroll
        for (int kc = 0; kc < 16; ++kc) {
            float4 a = *(const float4*)&As[kc][tig * 4];
            float4 b = *(const float4*)&Bs[kc][tjg * 4];
            acc[0][0] = fmaf(a.x, b.x, acc[0][0]); acc[0][1] = fmaf(a.x, b.y, acc[0][1]);
            acc[0][2] = fmaf(a.x, b.z, acc[0][2]); acc[0][3] = fmaf(a.x, b.w, acc[0][3]);
            acc[1][0] = fmaf(a.y, b.x, acc[1][0]); acc[1][1] = fmaf(a.y, b.y, acc[1][1]);
            acc[1][2] = fmaf(a.y, b.z, acc[1][2]); acc[1][3] = fmaf(a.y, b.w, acc[1][3]);
            acc[2][0] = fmaf(a.z, b.x, acc[2][0]); acc[2][1] = fmaf(a.z, b.y, acc[2][1]);
            acc[2][2] = fmaf(a.z, b.z, acc[2][2]); acc[2][3] = fmaf(a.z, b.w, acc[2][3]);
            acc[3][0] = fmaf(a.w, b.x, acc[3][0]); acc[3][1] = fmaf(a.w, b.y, acc[3][1]);
            acc[3][2] = fmaf(a.w, b.z, acc[3][2]); acc[3][3] = fmaf(a.w, b.w, acc[3][3]);
        }
    }

#pragma unroll
    for (int r = 0; r < 4; ++r) {
        int gi = m0 + tig * 4 + r;
#pragma unroll
        for (int c = 0; c < 4; ++c) {
            int gj = n0 + tjg * 4 + c;
            float v = acc[r][c];
            if (bias) v += bias[gj];
            if (res)  v += res[(size_t)gi * N + gj];
            if (doRelu) v = fmaxf(v, 0.0f);
            C[(size_t)gi * N + gj] = v;
        }
    }
}

// ---------------------------------------------------------------------------
// Transpose: positive[j][c][k] (k contiguous) -> posT[k][r] with r = j*256+c.
// Plain [R=131072, 256] -> [256, R] tiled transpose.
// ---------------------------------------------------------------------------
__global__ void __launch_bounds__(256)
transpose_kernel(const float* __restrict__ in, float* __restrict__ out)
{
    __shared__ float tile[32][33];
    const int rbase = blockIdx.x * 32;
    const int kbase = blockIdx.y * 32;
    const int tx = threadIdx.x;   // 0..31
    const int ty = threadIdx.y;   // 0..7

#pragma unroll
    for (int m = 0; m < 4; ++m) {
        int r = rbase + ty + m * 8;
        tile[ty + m * 8][tx] = in[(size_t)r * 256 + kbase + tx];
    }
    __syncthreads();
#pragma unroll
    for (int m = 0; m < 4; ++m) {
        int k = kbase + ty + m * 8;
        out[(size_t)k * (BSZ * LOCAL) + rbase + tx] = tile[tx][ty + m * 8];
    }
}

// ---------------------------------------------------------------------------
// Batched contrast GEMM with fused row-max subtraction.
// Each CTA: one k (of 256), one 64-row i-tile, ALL j=512 columns.
// 256 threads, 4x4 microtile via packed f32x2 FMA, K=256 in steps of 16,
// register double-buffered SMEM staging. Output tile buffered in SMEM.
// ---------------------------------------------------------------------------
#define CK_SMEM_FLOATS (2*16*64 + 2*16*64 + 64*512 + 64)   // 36928
#define CK_SMEM_BYTES  (CK_SMEM_FLOATS * 4)                 // 147712

__global__ void __launch_bounds__(256)
contrast_kernel(const float* __restrict__ pred,
                const float* __restrict__ posT,
                float* __restrict__ out)
{
    extern __shared__ float sm[];
    float* As     = sm;              // [2][16][64]
    float* Bs     = sm + 2048;       // [2][16][64]
    float* ob     = sm + 4096;       // [64][512]
    float* rowmax = sm + 4096 + 32768;

    const int tid = threadIdx.x;
    const int k   = blockIdx.x >> 3;
    const int i0  = (blockIdx.x & 7) << 6;

    const int tig = tid >> 4;        // 0..15
    const int tjg = tid & 15;        // 0..15
    const int lrow = tid >> 2;       // 0..63
    const int lq   = tid & 3;        // 0..3
    const int c0   = lq * 4;

    const float* Abase = pred + (size_t)(i0 + lrow) * LATENT + c0;
    const float* Bk    = posT + (size_t)k * (BSZ * LOCAL);

    float mx[4] = { -3.402823466e38f, -3.402823466e38f,
                    -3.402823466e38f, -3.402823466e38f };

    for (int jt = 0; jt < 8; ++jt) {
        const int j0 = jt << 6;
        const float* Bbase = Bk + (size_t)(j0 + lrow) * LOCAL + c0;

        unsigned long long acc[4][2] = {};

        // preload K-step 0 into buffer 0
        {
            float4 ra = *(const float4*)(Abase);
            float4 rb = *(const float4*)(Bbase);
            As[(c0 + 0) * 64 + lrow] = ra.x; As[(c0 + 1) * 64 + lrow] = ra.y;
            As[(c0 + 2) * 64 + lrow] = ra.z; As[(c0 + 3) * 64 + lrow] = ra.w;
            Bs[(c0 + 0) * 64 + lrow] = rb.x; Bs[(c0 + 1) * 64 + lrow] = rb.y;
            Bs[(c0 + 2) * 64 + lrow] = rb.z; Bs[(c0 + 3) * 64 + lrow] = rb.w;
        }
        __syncthreads();

        int buf = 0;
#pragma unroll 1
        for (int ks = 0; ks < 16; ++ks) {
            float4 na, nb;
            if (ks < 15) {
                na = *(const float4*)(Abase + (ks + 1) * 16);
                nb = *(const float4*)(Bbase + (ks + 1) * 16);
            }
            const float* Ab = As + buf * 1024;
            const float* Bb = Bs + buf * 1024;
#pragma unroll
            for (int kc = 0; kc < 16; ++kc) {
                float4 a = *(const float4*)(Ab + kc * 64 + tig * 4);
                ulonglong2 b = *(const ulonglong2*)(Bb + kc * 64 + tjg * 4);
                unsigned long long a0 = bc2(a.x), a1 = bc2(a.y);
                unsigned long long a2 = bc2(a.z), a3 = bc2(a.w);
                fma2(acc[0][0], a0, b.x); fma2(acc[0][1], a0, b.y);
                fma2(acc[1][0], a1, b.x); fma2(acc[1][1], a1, b.y);
                fma2(acc[2][0], a2, b.x); fma2(acc[2][1], a2, b.y);
                fma2(acc[3][0], a3, b.x); fma2(acc[3][1], a3, b.y);
            }
            if (ks < 15) {
                const int nbuf = buf ^ 1;
                float* An = As + nbuf * 1024;
                float* Bn = Bs + nbuf * 1024;
                An[(c0 + 0) * 64 + lrow] = na.x; An[(c0 + 1) * 64 + lrow] = na.y;
                An[(c0 + 2) * 64 + lrow] = na.z; An[(c0 + 3) * 64 + lrow] = na.w;
                Bn[(c0 + 0) * 64 + lrow] = nb.x; Bn[(c0 + 1) * 64 + lrow] = nb.y;
                Bn[(c0 + 2) * 64 + lrow] = nb.z; Bn[(c0 + 3) * 64 + lrow] = nb.w;
                __syncthreads();
                buf = nbuf;
            }
        }

        // stash tile into SMEM buffer, track running row max
#pragma unroll
        for (int r = 0; r < 4; ++r) {
            float2 v0 = up2(acc[r][0]);
            float2 v1 = up2(acc[r][1]);
            mx[r] = fmaxf(mx[r], fmaxf(fmaxf(v0.x, v0.y), fmaxf(v1.x, v1.y)));
            float4 v = make_float4(v0.x, v0.y, v1.x, v1.y);
            *(float4*)&ob[(tig * 4 + r) * 512 + j0 + tjg * 4] = v;
        }
        __syncthreads();
    }

    // reduce mx across the 16 tjg lanes of each tig group (within half-warp)
#pragma unroll
    for (int r = 0; r < 4; ++r) {
        float m = mx[r];
        m = fmaxf(m, __shfl_xor_sync(0xffffffffu, m, 1));
        m = fmaxf(m, __shfl_xor_sync(0xffffffffu, m, 2));
        m = fmaxf(m, __shfl_xor_sync(0xffffffffu, m, 4));
        m = fmaxf(m, __shfl_xor_sync(0xffffffffu, m, 8));
        mx[r] = m;
    }
    if (tjg == 0) {
        rowmax[tig * 4 + 0] = mx[0];
        rowmax[tig * 4 + 1] = mx[1];
        rowmax[tig * 4 + 2] = mx[2];
        rowmax[tig * 4 + 3] = mx[3];
    }
    __syncthreads();

    // subtract row max and stream the 64x512 tile out (coalesced float4)
    const size_t base = ((size_t)k * BSZ + i0) * BSZ;
#pragma unroll
    for (int v = 0; v < 32; ++v) {
        int lin = v * 256 + tid;       // 0..8191 float4 slots
        int i   = lin >> 7;            // 0..63
        int jq  = lin & 127;           // 0..127 float4 within row
        float4 val = *(const float4*)&ob[i * 512 + jq * 4];
        float m = rowmax[i];
        val.x -= m; val.y -= m; val.z -= m; val.w -= m;
        *(float4*)(out + base + (size_t)i * 512 + jq * 4) = val;
    }
}

// ---------------------------------------------------------------------------
// Launch
// ---------------------------------------------------------------------------
extern "C" void kernel_launch(void* const* d_in, const int* in_sizes, int n_in,
                              void* d_out, int out_size)
{
    const float* anchor   = (const float*)d_in[0];   // [512, 256]
    const float* positive = (const float*)d_in[1];   // [512, 256, 16, 16]
    const float* W1       = (const float*)d_in[2];   // [256, 512]
    const float* b1       = (const float*)d_in[3];   // [512]
    const float* W2       = (const float*)d_in[4];   // [512, 256]
    const float* b2       = (const float*)d_in[5];   // [256]
    const float* Wc       = (const float*)d_in[6];   // [256, 256]
    float* out            = (float*)d_out;           // [256, 512, 512]

    float *hp, *ap, *pp, *tp;
    cudaGetSymbolAddress((void**)&hp, g_h);
    cudaGetSymbolAddress((void**)&ap, g_a);
    cudaGetSymbolAddress((void**)&pp, g_pred);
    cudaGetSymbolAddress((void**)&tp, g_posT);

    cudaFuncSetAttribute(contrast_kernel,
                         cudaFuncAttributeMaxDynamicSharedMemorySize,
                         CK_SMEM_BYTES);

    // 1) h = relu(anchor @ W1 + b1)         [512, 512], K=256
    gemm_tile<<<dim3(HIDDEN / 64, BSZ / 64), 256>>>(
        anchor, W1, b1, nullptr, hp, BSZ, HIDDEN, LATENT, 1);

    // 2) a = anchor + h @ W2 + b2           [512, 256], K=512
    gemm_tile<<<dim3(LATENT / 64, BSZ / 64), 256>>>(
        hp, W2, b2, anchor, ap, BSZ, LATENT, HIDDEN, 0);

    // 3) pred = a @ Wc                      [512, 256], K=256
    gemm_tile<<<dim3(LOCAL / 64, BSZ / 64), 256>>>(
        ap, Wc, nullptr, nullptr, pp, BSZ, LOCAL, LATENT, 0);

    // 4) posT[k][j][c] = positive[j][c][k]
    transpose_kernel<<<dim3((BSZ * LOCAL) / 32, HW / 32), dim3(32, 8)>>>(
        positive, tp);

    // 5) logits + fused row-max subtraction
    contrast_kernel<<<HW * (BSZ / 64), 256, CK_SMEM_BYTES>>>(pp, tp, out);
}

// round 3
// speedup vs baseline: 1.0059x; 1.0059x over previous
#include <cuda_runtime.h>
#include <cuda_bf16.h>
#include <cstdint>
#include <cstddef>

// ---------------------------------------------------------------------------
// Problem shapes (fixed)
// B=512, LATENT=256, LOCAL=256, HIDDEN=512, H=W=16 -> HW=256
// out[k][i][j] = sum_c pred[i][c] * positive[j][c][k]  - rowmax_j
// ---------------------------------------------------------------------------

#define BSZ     512
#define LATENT  256
#define LOCAL   256
#define HIDDEN  512
#define HW      256

// Scratch (static device allocations are allowed; cudaMalloc is not)
__device__ float g_h[BSZ * HIDDEN];                       // hidden activations
__device__ float g_a[BSZ * LATENT];                       // residual MLP out
__device__ float g_pred[BSZ * LOCAL];                     // pred = a @ Wc
__device__ float g_posT[(size_t)HW * BSZ * LOCAL];        // posT[k][j][c], 128 MB

// ---------------------------------------------------------------------------
// f32x2 packed helpers (Blackwell sm_103a)
// ---------------------------------------------------------------------------
__device__ __forceinline__ unsigned long long bc2(float x) {
    unsigned long long r;
    unsigned u = __float_as_uint(x);
    asm("mov.b64 %0, {%1, %1};" : "=l"(r) : "r"(u));
    return r;
}
__device__ __forceinline__ void fma2(unsigned long long& d,
                                     unsigned long long a,
                                     unsigned long long b) {
    asm("fma.rn.f32x2 %0, %1, %2, %0;" : "+l"(d) : "l"(a), "l"(b));
}
__device__ __forceinline__ float2 up2(unsigned long long v) {
    float2 f;
    asm("mov.b64 {%0, %1}, %2;" : "=f"(f.x), "=f"(f.y) : "l"(v));
    return f;
}

// ---------------------------------------------------------------------------
// Generic small fp32 GEMM: C[M,N] = act(A[M,K] @ B[K,N] + bias + res)
// 64x64 tile, 256 threads, 4x4 microtile, K-step 16.
// ---------------------------------------------------------------------------
__global__ void __launch_bounds__(256)
gemm_tile(const float* __restrict__ A, const float* __restrict__ B,
          const float* __restrict__ bias, const float* __restrict__ res,
          float* __restrict__ C, int M, int N, int K, int doRelu)
{
    __shared__ float As[16][64];   // [k][m]  (transposed on store)
    __shared__ float Bs[16][64];   // [k][n]

    const int tid = threadIdx.x;
    const int tig = tid >> 4;      // 0..15 -> i rows tig*4..+3
    const int tjg = tid & 15;      // 0..15 -> j cols tjg*4..+3
    const int m0  = blockIdx.y * 64;
    const int n0  = blockIdx.x * 64;

    const int arow = tid >> 2, aq = tid & 3;    // A tile: 64 rows x 4 quads
    const int brow = tid >> 4, bq = tid & 15;   // B tile: 16 rows x 16 quads

    float acc[4][4] = {};

    for (int kk = 0; kk < K; kk += 16) {
        float4 av = *(const float4*)(A + (size_t)(m0 + arow) * K + kk + aq * 4);
        float4 bv = *(const float4*)(B + (size_t)(kk + brow) * N + n0 + bq * 4);
        __syncthreads();
        As[aq * 4 + 0][arow] = av.x;
        As[aq * 4 + 1][arow] = av.y;
        As[aq * 4 + 2][arow] = av.z;
        As[aq * 4 + 3][arow] = av.w;
        *(float4*)&Bs[brow][bq * 4] = bv;
        __syncthreads();
#pragma unroll
        for (int kc = 0; kc < 16; ++kc) {
            float4 a = *(const float4*)&As[kc][tig * 4];
            float4 b = *(const float4*)&Bs[kc][tjg * 4];
            acc[0][0] = fmaf(a.x, b.x, acc[0][0]); acc[0][1] = fmaf(a.x, b.y, acc[0][1]);
            acc[0][2] = fmaf(a.x, b.z, acc[0][2]); acc[0][3] = fmaf(a.x, b.w, acc[0][3]);
            acc[1][0] = fmaf(a.y, b.x, acc[1][0]); acc[1][1] = fmaf(a.y, b.y, acc[1][1]);
            acc[1][2] = fmaf(a.y, b.z, acc[1][2]); acc[1][3] = fmaf(a.y, b.w, acc[1][3]);
            acc[2][0] = fmaf(a.z, b.x, acc[2][0]); acc[2][1] = fmaf(a.z, b.y, acc[2][1]);
            acc[2][2] = fmaf(a.z, b.z, acc[2][2]); acc[2][3] = fmaf(a.z, b.w, acc[2][3]);
            acc[3][0] = fmaf(a.w, b.x, acc[3][0]); acc[3][1] = fmaf(a.w, b.y, acc[3][1]);
            acc[3][2] = fmaf(a.w, b.z, acc[3][2]); acc[3][3] = fmaf(a.w, b.w, acc[3][3]);
        }
    }

#pragma unroll
    for (int r = 0; r < 4; ++r) {
        int gi = m0 + tig * 4 + r;
#pragma unroll
        for (int c = 0; c < 4; ++c) {
            int gj = n0 + tjg * 4 + c;
            float v = acc[r][c];
            if (bias) v += bias[gj];
            if (res)  v += res[(size_t)gi * N + gj];
            if (doRelu) v = fmaxf(v, 0.0f);
            C[(size_t)gi * N + gj] = v;
        }
    }
}

// ---------------------------------------------------------------------------
// Transpose: positive[j][c][k] (k contiguous) -> posT[k][r] with r = j*256+c.
// Plain [R=131072, 256] -> [256, R] tiled transpose.
// ---------------------------------------------------------------------------
__global__ void __launch_bounds__(256)
transpose_kernel(const float* __restrict__ in, float* __restrict__ out)
{
    __shared__ float tile[32][33];
    const int rbase = blockIdx.x * 32;
    const int kbase = blockIdx.y * 32;
    const int tx = threadIdx.x;   // 0..31
    const int ty = threadIdx.y;   // 0..7

#pragma unroll
    for (int m = 0; m < 4; ++m) {
        int r = rbase + ty + m * 8;
        tile[ty + m * 8][tx] = in[(size_t)r * 256 + kbase + tx];
    }
    __syncthreads();
#pragma unroll
    for (int m = 0; m < 4; ++m) {
        int k = kbase + ty + m * 8;
        out[(size_t)k * (BSZ * LOCAL) + rbase + tx] = tile[tx][ty + m * 8];
    }
}

// ---------------------------------------------------------------------------
// Batched contrast GEMM with fused row-max subtraction.
// Each CTA: one k (of 256), one 64-row i-tile, ALL j=512 columns.
// 256 threads, 4x4 microtile via packed f32x2 FMA, K=256 in steps of 16,
// register double-buffered SMEM staging. Output tile buffered in SMEM.
// ---------------------------------------------------------------------------
#define CK_SMEM_FLOATS (2*16*64 + 2*16*64 + 64*512 + 64)   // 36928
#define CK_SMEM_BYTES  (CK_SMEM_FLOATS * 4)                 // 147712

__global__ void __launch_bounds__(256)
contrast_kernel(const float* __restrict__ pred,
                const float* __restrict__ posT,
                float* __restrict__ out)
{
    extern __shared__ float sm[];
    float* As     = sm;              // [2][16][64]
    float* Bs     = sm + 2048;       // [2][16][64]
    float* ob     = sm + 4096;       // [64][512]
    float* rowmax = sm + 4096 + 32768;

    const int tid = threadIdx.x;
    const int k   = blockIdx.x >> 3;
    const int i0  = (blockIdx.x & 7) << 6;

    const int tig = tid >> 4;        // 0..15
    const int tjg = tid & 15;        // 0..15
    const int lrow = tid >> 2;       // 0..63
    const int lq   = tid & 3;        // 0..3
    const int c0   = lq * 4;

    const float* Abase = pred + (size_t)(i0 + lrow) * LATENT + c0;
    const float* Bk    = posT + (size_t)k * (BSZ * LOCAL);

    float mx[4] = { -3.402823466e38f, -3.402823466e38f,
                    -3.402823466e38f, -3.402823466e38f };

    for (int jt = 0; jt < 8; ++jt) {
        const int j0 = jt << 6;
        const float* Bbase = Bk + (size_t)(j0 + lrow) * LOCAL + c0;

        unsigned long long acc[4][2] = {};

        // preload K-step 0 into buffer 0
        {
            float4 ra = *(const float4*)(Abase);
            float4 rb = *(const float4*)(Bbase);
            As[(c0 + 0) * 64 + lrow] = ra.x; As[(c0 + 1) * 64 + lrow] = ra.y;
            As[(c0 + 2) * 64 + lrow] = ra.z; As[(c0 + 3) * 64 + lrow] = ra.w;
            Bs[(c0 + 0) * 64 + lrow] = rb.x; Bs[(c0 + 1) * 64 + lrow] = rb.y;
            Bs[(c0 + 2) * 64 + lrow] = rb.z; Bs[(c0 + 3) * 64 + lrow] = rb.w;
        }
        __syncthreads();

        int buf = 0;
#pragma unroll 1
        for (int ks = 0; ks < 16; ++ks) {
            float4 na, nb;
            if (ks < 15) {
                na = *(const float4*)(Abase + (ks + 1) * 16);
                nb = *(const float4*)(Bbase + (ks + 1) * 16);
            }
            const float* Ab = As + buf * 1024;
            const float* Bb = Bs + buf * 1024;
#pragma unroll
            for (int kc = 0; kc < 16; ++kc) {
                float4 a = *(const float4*)(Ab + kc * 64 + tig * 4);
                ulonglong2 b = *(const ulonglong2*)(Bb + kc * 64 + tjg * 4);
                unsigned long long a0 = bc2(a.x), a1 = bc2(a.y);
                unsigned long long a2 = bc2(a.z), a3 = bc2(a.w);
                fma2(acc[0][0], a0, b.x); fma2(acc[0][1], a0, b.y);
                fma2(acc[1][0], a1, b.x); fma2(acc[1][1], a1, b.y);
                fma2(acc[2][0], a2, b.x); fma2(acc[2][1], a2, b.y);
                fma2(acc[3][0], a3, b.x); fma2(acc[3][1], a3, b.y);
            }
            if (ks < 15) {
                const int nbuf = buf ^ 1;
                float* An = As + nbuf * 1024;
                float* Bn = Bs + nbuf * 1024;
                An[(c0 + 0) * 64 + lrow] = na.x; An[(c0 + 1) * 64 + lrow] = na.y;
                An[(c0 + 2) * 64 + lrow] = na.z; An[(c0 + 3) * 64 + lrow] = na.w;
                Bn[(c0 + 0) * 64 + lrow] = nb.x; Bn[(c0 + 1) * 64 + lrow] = nb.y;
                Bn[(c0 + 2) * 64 + lrow] = nb.z; Bn[(c0 + 3) * 64 + lrow] = nb.w;
                __syncthreads();
                buf = nbuf;
            }
        }

        // stash tile into SMEM buffer, track running row max
#pragma unroll
        for (int r = 0; r < 4; ++r) {
            float2 v0 = up2(acc[r][0]);
            float2 v1 = up2(acc[r][1]);
            mx[r] = fmaxf(mx[r], fmaxf(fmaxf(v0.x, v0.y), fmaxf(v1.x, v1.y)));
            float4 v = make_float4(v0.x, v0.y, v1.x, v1.y);
            *(float4*)&ob[(tig * 4 + r) * 512 + j0 + tjg * 4] = v;
        }
        __syncthreads();
    }

    // reduce mx across the 16 tjg lanes of each tig group (within half-warp)
#pragma unroll
    for (int r = 0; r < 4; ++r) {
        float m = mx[r];
        m = fmaxf(m, __shfl_xor_sync(0xffffffffu, m, 1));
        m = fmaxf(m, __shfl_xor_sync(0xffffffffu, m, 2));
        m = fmaxf(m, __shfl_xor_sync(0xffffffffu, m, 4));
        m = fmaxf(m, __shfl_xor_sync(0xffffffffu, m, 8));
        mx[r] = m;
    }
    if (tjg == 0) {
        rowmax[tig * 4 + 0] = mx[0];
        rowmax[tig * 4 + 1] = mx[1];
        rowmax[tig * 4 + 2] = mx[2];
        rowmax[tig * 4 + 3] = mx[3];
    }
    __syncthreads();

    // subtract row max and stream the 64x512 tile out (coalesced float4)
    const size_t base = ((size_t)k * BSZ + i0) * BSZ;
#pragma unroll
    for (int v = 0; v < 32; ++v) {
        int lin = v * 256 + tid;       // 0..8191 float4 slots
        int i   = lin >> 7;            // 0..63
        int jq  = lin & 127;           // 0..127 float4 within row
        float4 val = *(const float4*)&ob[i * 512 + jq * 4];
        float m = rowmax[i];
        val.x -= m; val.y -= m; val.z -= m; val.w -= m;
        *(float4*)(out + base + (size_t)i * 512 + jq * 4) = val;
    }
}

// ---------------------------------------------------------------------------
// Launch
// ---------------------------------------------------------------------------
extern "C" void kernel_launch(void* const* d_in, const int* in_sizes, int n_in,
                              void* d_out, int out_size)
{
    const float* anchor   = (const float*)d_in[0];   // [512, 256]
    const float* positive = (const float*)d_in[1];   // [512, 256, 16, 16]
    const float* W1       = (const float*)d_in[2];   // [256, 512]
    const float* b1       = (const float*)d_in[3];   // [512]
    const float* W2       = (const float*)d_in[4];   // [512, 256]
    const float* b2       = (const float*)d_in[5];   // [256]
    const float* Wc       = (const float*)d_in[6];   // [256, 256]
    float* out            = (float*)d_out;           // [256, 512, 512]

    float *hp, *ap, *pp, *tp;
    cudaGetSymbolAddress((void**)&hp, g_h);
    cudaGetSymbolAddress((void**)&ap, g_a);
    cudaGetSymbolAddress((void**)&pp, g_pred);
    cudaGetSymbolAddress((void**)&tp, g_posT);

    cudaFuncSetAttribute(contrast_kernel,
                         cudaFuncAttributeMaxDynamicSharedMemorySize,
                         CK_SMEM_BYTES);

    // 1) h = relu(anchor @ W1 + b1)         [512, 512], K=256
    gemm_tile<<<dim3(HIDDEN / 64, BSZ / 64), 256>>>(
        anchor, W1, b1, nullptr, hp, BSZ, HIDDEN, LATENT, 1);

    // 2) a = anchor + h @ W2 + b2           [512, 256], K=512
    gemm_tile<<<dim3(LATENT / 64, BSZ / 64), 256>>>(
        hp, W2, b2, anchor, ap, BSZ, LATENT, HIDDEN, 0);

    // 3) pred = a @ Wc                      [512, 256], K=256
    gemm_tile<<<dim3(LOCAL / 64, BSZ / 64), 256>>>(
        ap, Wc, nullptr, nullptr, pp, BSZ, LOCAL, LATENT, 0);

    // 4) posT[k][j][c] = positive[j][c][k]
    transpose_kernel<<<dim3((BSZ * LOCAL) / 32, HW / 32), dim3(32, 8)>>>(
        positive, tp);

    // 5) logits + fused row-max subtraction
    contrast_kernel<<<HW * (BSZ / 64), 256, CK_SMEM_BYTES>>>(pp, tp, out);
}

// round 5
// speedup vs baseline: 2.2839x; 2.2705x over previous
#include <cuda_runtime.h>
#include <cuda_bf16.h>
#include <cstdint>
#include <cstddef>

// ---------------------------------------------------------------------------
// Shapes: B=512, LATENT=LOCAL=256, HIDDEN=512, HW=256
// out[k][i][j] = sum_c pred[i][c] * positive[j][c][k]  - rowmax_j
// Contrast GEMM on mma.sync bf16 (HMMA) with hi/lo split folded into K'=768:
//   predX segs = (hi, lo, hi), posX segs = (hi, hi, lo)
//   => ahi*bhi + alo*bhi + ahi*blo ~= a*b   (error ~2^-18 per product)
// (tcgen05 is unusable here: harness PTX targets sm_103 without the 'a'
//  feature set, so only generic-target tensor instructions compile.)
// ---------------------------------------------------------------------------

#define BSZ     512
#define LATENT  256
#define HIDDEN  512
#define HW      256
#define KP      768

__device__ float          g_h[BSZ * HIDDEN];
__device__ float          g_a[BSZ * LATENT];
__device__ float          g_pred[BSZ * LATENT];
__device__ __nv_bfloat16  g_predX[BSZ * KP];                 // 768 KB
__device__ __nv_bfloat16  g_posX[(size_t)HW * BSZ * KP];     // 192 MB

// ---------------------------------------------------------------------------
// PTX helpers (generic-target only: cp.async, ldmatrix, mma.sync)
// ---------------------------------------------------------------------------
__device__ __forceinline__ uint32_t smem_u32(const void* p) {
    uint32_t a;
    asm("{ .reg .u64 t; cvta.to.shared.u64 t, %1; cvt.u32.u64 %0, t; }"
        : "=r"(a) : "l"(p));
    return a;
}
__device__ __forceinline__ void cp16(uint32_t dst, const void* src) {
    asm volatile("cp.async.cg.shared.global [%0], [%1], 16;"
                 :: "r"(dst), "l"(src) : "memory");
}
#define CP_COMMIT() asm volatile("cp.async.commit_group;" ::: "memory")
#define CP_WAIT(N)  asm volatile("cp.async.wait_group %0;" :: "n"(N) : "memory")

__device__ __forceinline__ void ldmx4(uint32_t& r0, uint32_t& r1,
                                      uint32_t& r2, uint32_t& r3,
                                      uint32_t addr) {
    asm volatile("ldmatrix.sync.aligned.m8n8.x4.shared.b16 {%0,%1,%2,%3}, [%4];"
                 : "=r"(r0), "=r"(r1), "=r"(r2), "=r"(r3) : "r"(addr));
}
__device__ __forceinline__ void mma16816(float* c,
                                         uint32_t a0, uint32_t a1,
                                         uint32_t a2, uint32_t a3,
                                         uint32_t b0, uint32_t b1) {
    asm volatile("mma.sync.aligned.m16n8k16.row.col.f32.bf16.bf16.f32 "
                 "{%0,%1,%2,%3}, {%4,%5,%6,%7}, {%8,%9}, {%0,%1,%2,%3};"
                 : "+f"(c[0]), "+f"(c[1]), "+f"(c[2]), "+f"(c[3])
                 : "r"(a0), "r"(a1), "r"(a2), "r"(a3), "r"(b0), "r"(b1));
}

// ---------------------------------------------------------------------------
// Small fp32 GEMM for the MLP chain (passing since R1)
// ---------------------------------------------------------------------------
__global__ void __launch_bounds__(256)
gemm_tile(const float* __restrict__ A, const float* __restrict__ B,
          const float* __restrict__ bias, const float* __restrict__ res,
          float* __restrict__ C, int M, int N, int K, int doRelu)
{
    __shared__ float As[16][64];
    __shared__ float Bs[16][64];

    const int tid = threadIdx.x;
    const int tig = tid >> 4, tjg = tid & 15;
    const int m0 = blockIdx.y * 64, n0 = blockIdx.x * 64;
    const int arow = tid >> 2, aq = tid & 3;
    const int brow = tid >> 4, bq = tid & 15;

    float acc[4][4] = {};

    for (int kk = 0; kk < K; kk += 16) {
        float4 av = *(const float4*)(A + (size_t)(m0 + arow) * K + kk + aq * 4);
        float4 bv = *(const float4*)(B + (size_t)(kk + brow) * N + n0 + bq * 4);
        __syncthreads();
        As[aq * 4 + 0][arow] = av.x; As[aq * 4 + 1][arow] = av.y;
        As[aq * 4 + 2][arow] = av.z; As[aq * 4 + 3][arow] = av.w;
        *(float4*)&Bs[brow][bq * 4] = bv;
        __syncthreads();
#pragma unroll
        for (int kc = 0; kc < 16; ++kc) {
            float4 a = *(const float4*)&As[kc][tig * 4];
            float4 b = *(const float4*)&Bs[kc][tjg * 4];
            acc[0][0] = fmaf(a.x, b.x, acc[0][0]); acc[0][1] = fmaf(a.x, b.y, acc[0][1]);
            acc[0][2] = fmaf(a.x, b.z, acc[0][2]); acc[0][3] = fmaf(a.x, b.w, acc[0][3]);
            acc[1][0] = fmaf(a.y, b.x, acc[1][0]); acc[1][1] = fmaf(a.y, b.y, acc[1][1]);
            acc[1][2] = fmaf(a.y, b.z, acc[1][2]); acc[1][3] = fmaf(a.y, b.w, acc[1][3]);
            acc[2][0] = fmaf(a.z, b.x, acc[2][0]); acc[2][1] = fmaf(a.z, b.y, acc[2][1]);
            acc[2][2] = fmaf(a.z, b.z, acc[2][2]); acc[2][3] = fmaf(a.z, b.w, acc[2][3]);
            acc[3][0] = fmaf(a.w, b.x, acc[3][0]); acc[3][1] = fmaf(a.w, b.y, acc[3][1]);
            acc[3][2] = fmaf(a.w, b.z, acc[3][2]); acc[3][3] = fmaf(a.w, b.w, acc[3][3]);
        }
    }

#pragma unroll
    for (int r = 0; r < 4; ++r) {
        int gi = m0 + tig * 4 + r;
#pragma unroll
        for (int c = 0; c < 4; ++c) {
            int gj = n0 + tjg * 4 + c;
            float v = acc[r][c];
            if (bias) v += bias[gj];
            if (res)  v += res[(size_t)gi * N + gj];
            if (doRelu) v = fmaxf(v, 0.0f);
            C[(size_t)gi * N + gj] = v;
        }
    }
}

// ---------------------------------------------------------------------------
// predX[i][c'] segs (hi, lo, hi) from fp32 pred
// ---------------------------------------------------------------------------
__global__ void __launch_bounds__(256)
predsplit_kernel(const float* __restrict__ pred, __nv_bfloat16* __restrict__ out)
{
    int i = blockIdx.x, c = threadIdx.x;
    float v = pred[i * 256 + c];
    __nv_bfloat16 hi = __float2bfloat16(v);
    __nv_bfloat16 lo = __float2bfloat16(v - __bfloat162float(hi));
    size_t base = (size_t)i * KP;
    out[base + c] = hi;
    out[base + 256 + c] = lo;
    out[base + 512 + c] = hi;
}

// ---------------------------------------------------------------------------
// posX[k][j][c'] segs (hi, hi, lo) from positive[j][c][k] (transpose+split)
// ---------------------------------------------------------------------------
__global__ void __launch_bounds__(256)
possplit_kernel(const float* __restrict__ in, __nv_bfloat16* __restrict__ out)
{
    __shared__ float tile[32][33];
    const int rbase = blockIdx.x * 32;
    const int kbase = blockIdx.y * 32;
    const int tx = threadIdx.x, ty = threadIdx.y;

#pragma unroll
    for (int m = 0; m < 4; ++m)
        tile[ty + m * 8][tx] = in[(size_t)(rbase + ty + m * 8) * 256 + kbase + tx];
    __syncthreads();
#pragma unroll
    for (int m = 0; m < 4; ++m) {
        int k = kbase + ty + m * 8;
        int r = rbase + tx;
        int j = r >> 8, c = r & 255;
        float v = tile[tx][ty + m * 8];
        __nv_bfloat16 hi = __float2bfloat16(v);
        __nv_bfloat16 lo = __float2bfloat16(v - __bfloat162float(hi));
        size_t base = ((size_t)k * BSZ + j) * KP;
        out[base + c] = hi;
        out[base + 256 + c] = hi;
        out[base + 512 + c] = lo;
    }
}

// ---------------------------------------------------------------------------
// HMMA contrast kernel. CTA = (k, 64-row i-tile), full j=512, K'=768.
// 8 warps = 4 i-groups(16) x 2 j-groups(256). 128 fp32 acc regs/thread.
// SMEM: double-buffered {A 64x32, B 512x32} bf16, 80B padded rows
// (conflict-free ldmatrix), cp.async pipeline, fused row-max epilogue.
// ---------------------------------------------------------------------------
#define AST     80                     // padded SMEM row stride (bytes)
#define OF_A0   0
#define OF_A1   (64 * AST)             // 5120
#define OF_B0   (2 * 64 * AST)         // 10240
#define OF_B1   (OF_B0 + 512 * AST)    // 51200
#define OF_RMX  (OF_B0 + 2 * 512 * AST)// 92160
#define CT_SMEM (OF_RMX + 512 + 128)

__global__ void __launch_bounds__(256, 1)
contrast_mma(const __nv_bfloat16* __restrict__ predX,
             const __nv_bfloat16* __restrict__ posX,
             float* __restrict__ out)
{
    extern __shared__ char smem[];
    const uint32_t sb = smem_u32(smem);
    const int tid = threadIdx.x;
    const int wid = tid >> 5, lid = tid & 31;
    const int k  = blockIdx.x >> 3;
    const int i0 = (blockIdx.x & 7) << 6;

    const int iw = (wid & 3) * 16;     // warp's i offset (0..48)
    const int jw = (wid >> 2) * 256;   // warp's j offset (0 or 256)

    // loader indices: 64 row-groups x 4 16B quads
    const int r = tid >> 2, q = tid & 3;
    const char* Ab = (const char*)(predX + (size_t)i0 * KP);
    const char* Bb = (const char*)(posX + (size_t)k * BSZ * KP);

    float acc[32][4];
#pragma unroll
    for (int t = 0; t < 32; ++t) {
        acc[t][0] = 0.f; acc[t][1] = 0.f; acc[t][2] = 0.f; acc[t][3] = 0.f;
    }

    auto loadChunk = [&](int n, int buf) {
        const uint32_t at = sb + (buf ? OF_A1 : OF_A0);
        const uint32_t bt = sb + (buf ? OF_B1 : OF_B0);
        const size_t co = (size_t)n * 64 + q * 16;
        cp16(at + r * AST + q * 16, Ab + (size_t)r * (KP * 2) + co);
#pragma unroll
        for (int it = 0; it < 8; ++it) {
            int row = r + it * 64;
            cp16(bt + row * AST + q * 16, Bb + (size_t)row * (KP * 2) + co);
        }
        CP_COMMIT();
    };

    // ldmatrix base addresses for this lane
    const uint32_t lA = (uint32_t)((iw + (lid & 15)) * AST + (lid >> 4) * 16);
    const uint32_t lB = (uint32_t)((jw + (lid & 15)) * AST + (lid >> 4) * 16);

    loadChunk(0, 0);

#pragma unroll 1
    for (int n = 0; n < 24; ++n) {
        const int buf = n & 1;
        if (n < 23) { loadChunk(n + 1, buf ^ 1); CP_WAIT(1); }
        else        { CP_WAIT(0); }
        __syncthreads();

        const uint32_t at = sb + (buf ? OF_A1 : OF_A0) + lA;
        const uint32_t bt = sb + (buf ? OF_B1 : OF_B0) + lB;
#pragma unroll
        for (int ks = 0; ks < 2; ++ks) {
            uint32_t a0, a1, a2, a3;
            ldmx4(a0, a1, a2, a3, at + ks * 32);
#pragma unroll
            for (int nt = 0; nt < 16; ++nt) {
                uint32_t b0, b1, b2, b3;
                ldmx4(b0, b1, b2, b3, bt + nt * 16 * AST + ks * 32);
                mma16816(acc[nt * 2 + 0], a0, a1, a2, a3, b0, b2);
                mma16816(acc[nt * 2 + 1], a0, a1, a2, a3, b1, b3);
            }
        }
        __syncthreads();   // before next-next load overwrites this buffer
    }

    // ---- fused row-max: thread rows = iw + lid/4 and +8 ----
    float mx0 = -3.402823466e38f, mx1 = -3.402823466e38f;
#pragma unroll
    for (int t = 0; t < 32; ++t) {
        mx0 = fmaxf(mx0, fmaxf(acc[t][0], acc[t][1]));
        mx1 = fmaxf(mx1, fmaxf(acc[t][2], acc[t][3]));
    }
    mx0 = fmaxf(mx0, __shfl_xor_sync(0xffffffffu, mx0, 1));
    mx0 = fmaxf(mx0, __shfl_xor_sync(0xffffffffu, mx0, 2));
    mx1 = fmaxf(mx1, __shfl_xor_sync(0xffffffffu, mx1, 1));
    mx1 = fmaxf(mx1, __shfl_xor_sync(0xffffffffu, mx1, 2));

    float* rmax = (float*)(smem + OF_RMX);   // [2 j-groups][64 rows]
    const int rl = iw + (lid >> 2);
    const int jg = wid >> 2;
    if ((lid & 3) == 0) {
        rmax[jg * 64 + rl]     = mx0;
        rmax[jg * 64 + rl + 8] = mx1;
    }
    __syncthreads();
    const float m0 = fmaxf(rmax[rl],     rmax[64 + rl]);
    const float m1 = fmaxf(rmax[rl + 8], rmax[64 + rl + 8]);

    // ---- subtract + store ----
    const size_t obase = ((size_t)k * BSZ + i0) * BSZ;
    float* o0 = out + obase + (size_t)rl * BSZ + jw + (lid & 3) * 2;
    float* o1 = o0 + (size_t)8 * BSZ;
#pragma unroll
    for (int nt = 0; nt < 32; ++nt) {
        float2 v0 = make_float2(acc[nt][0] - m0, acc[nt][1] - m0);
        float2 v1 = make_float2(acc[nt][2] - m1, acc[nt][3] - m1);
        *(float2*)(o0 + nt * 8) = v0;
        *(float2*)(o1 + nt * 8) = v1;
    }
}

// ---------------------------------------------------------------------------
// Launch
// ---------------------------------------------------------------------------
extern "C" void kernel_launch(void* const* d_in, const int* in_sizes, int n_in,
                              void* d_out, int out_size)
{
    const float* anchor   = (const float*)d_in[0];
    const float* positive = (const float*)d_in[1];
    const float* W1       = (const float*)d_in[2];
    const float* b1       = (const float*)d_in[3];
    const float* W2       = (const float*)d_in[4];
    const float* b2       = (const float*)d_in[5];
    const float* Wc       = (const float*)d_in[6];
    float* out            = (float*)d_out;

    float *hp, *ap, *pp;
    __nv_bfloat16 *px, *qx;
    cudaGetSymbolAddress((void**)&hp, g_h);
    cudaGetSymbolAddress((void**)&ap, g_a);
    cudaGetSymbolAddress((void**)&pp, g_pred);
    cudaGetSymbolAddress((void**)&qx, g_predX);
    cudaGetSymbolAddress((void**)&px, g_posX);

    cudaFuncSetAttribute(contrast_mma,
                         cudaFuncAttributeMaxDynamicSharedMemorySize, CT_SMEM);

    // MLP chain (fp32)
    gemm_tile<<<dim3(HIDDEN / 64, BSZ / 64), 256>>>(
        anchor, W1, b1, nullptr, hp, BSZ, HIDDEN, LATENT, 1);
    gemm_tile<<<dim3(LATENT / 64, BSZ / 64), 256>>>(
        hp, W2, b2, anchor, ap, BSZ, LATENT, HIDDEN, 0);
    gemm_tile<<<dim3(LATENT / 64, BSZ / 64), 256>>>(
        ap, Wc, nullptr, nullptr, pp, BSZ, LATENT, LATENT, 0);

    // hi/lo split prep
    predsplit_kernel<<<BSZ, 256>>>(pp, qx);
    possplit_kernel<<<dim3((BSZ * 256) / 32, HW / 32), dim3(32, 8)>>>(positive, px);

    // HMMA contrast GEMM + fused rowmax
    contrast_mma<<<HW * 8, 256, CT_SMEM>>>(qx, px, out);
}

// round 6
// speedup vs baseline: 2.3038x; 1.0087x over previous
#include <cuda_runtime.h>
#include <cuda_bf16.h>
#include <cstdint>
#include <cstddef>

// ---------------------------------------------------------------------------
// Shapes: B=512, LATENT=LOCAL=256, HIDDEN=512, HW=256
// out[k][i][j] = sum_c pred[i][c] * positive[j][c][k]  - rowmax_j
// Contrast GEMM on mma.sync bf16 (HMMA) with hi/lo split folded into K'=768:
//   predX segs = (hi, lo, hi), posX segs = (hi, hi, lo)
// R6: warp tile 64i x 64j (B fragments read once per CTA), 3-stage cp.async
// ring with a single __syncthreads per chunk.
// ---------------------------------------------------------------------------

#define BSZ     512
#define LATENT  256
#define HIDDEN  512
#define HW      256
#define KP      768

__device__ float          g_h[BSZ * HIDDEN];
__device__ float          g_a[BSZ * LATENT];
__device__ float          g_pred[BSZ * LATENT];
__device__ __nv_bfloat16  g_predX[BSZ * KP];                 // 768 KB
__device__ __nv_bfloat16  g_posX[(size_t)HW * BSZ * KP];     // 192 MB

// ---------------------------------------------------------------------------
// PTX helpers (generic-target only: cp.async, ldmatrix, mma.sync)
// ---------------------------------------------------------------------------
__device__ __forceinline__ uint32_t smem_u32(const void* p) {
    uint32_t a;
    asm("{ .reg .u64 t; cvta.to.shared.u64 t, %1; cvt.u32.u64 %0, t; }"
        : "=r"(a) : "l"(p));
    return a;
}
__device__ __forceinline__ void cp16(uint32_t dst, const void* src) {
    asm volatile("cp.async.cg.shared.global [%0], [%1], 16;"
                 :: "r"(dst), "l"(src) : "memory");
}
#define CP_COMMIT() asm volatile("cp.async.commit_group;" ::: "memory")
#define CP_WAIT(N)  asm volatile("cp.async.wait_group %0;" :: "n"(N) : "memory")

__device__ __forceinline__ void ldmx4(uint32_t& r0, uint32_t& r1,
                                      uint32_t& r2, uint32_t& r3,
                                      uint32_t addr) {
    asm volatile("ldmatrix.sync.aligned.m8n8.x4.shared.b16 {%0,%1,%2,%3}, [%4];"
                 : "=r"(r0), "=r"(r1), "=r"(r2), "=r"(r3) : "r"(addr));
}
__device__ __forceinline__ void mma16816(float* c,
                                         uint32_t a0, uint32_t a1,
                                         uint32_t a2, uint32_t a3,
                                         uint32_t b0, uint32_t b1) {
    asm volatile("mma.sync.aligned.m16n8k16.row.col.f32.bf16.bf16.f32 "
                 "{%0,%1,%2,%3}, {%4,%5,%6,%7}, {%8,%9}, {%0,%1,%2,%3};"
                 : "+f"(c[0]), "+f"(c[1]), "+f"(c[2]), "+f"(c[3])
                 : "r"(a0), "r"(a1), "r"(a2), "r"(a3), "r"(b0), "r"(b1));
}

// ---------------------------------------------------------------------------
// Small fp32 GEMM for the MLP chain
// ---------------------------------------------------------------------------
__global__ void __launch_bounds__(256)
gemm_tile(const float* __restrict__ A, const float* __restrict__ B,
          const float* __restrict__ bias, const float* __restrict__ res,
          float* __restrict__ C, int M, int N, int K, int doRelu)
{
    __shared__ float As[16][64];
    __shared__ float Bs[16][64];

    const int tid = threadIdx.x;
    const int tig = tid >> 4, tjg = tid & 15;
    const int m0 = blockIdx.y * 64, n0 = blockIdx.x * 64;
    const int arow = tid >> 2, aq = tid & 3;
    const int brow = tid >> 4, bq = tid & 15;

    float acc[4][4] = {};

    for (int kk = 0; kk < K; kk += 16) {
        float4 av = *(const float4*)(A + (size_t)(m0 + arow) * K + kk + aq * 4);
        float4 bv = *(const float4*)(B + (size_t)(kk + brow) * N + n0 + bq * 4);
        __syncthreads();
        As[aq * 4 + 0][arow] = av.x; As[aq * 4 + 1][arow] = av.y;
        As[aq * 4 + 2][arow] = av.z; As[aq * 4 + 3][arow] = av.w;
        *(float4*)&Bs[brow][bq * 4] = bv;
        __syncthreads();
#pragma unroll
        for (int kc = 0; kc < 16; ++kc) {
            float4 a = *(const float4*)&As[kc][tig * 4];
            float4 b = *(const float4*)&Bs[kc][tjg * 4];
            acc[0][0] = fmaf(a.x, b.x, acc[0][0]); acc[0][1] = fmaf(a.x, b.y, acc[0][1]);
            acc[0][2] = fmaf(a.x, b.z, acc[0][2]); acc[0][3] = fmaf(a.x, b.w, acc[0][3]);
            acc[1][0] = fmaf(a.y, b.x, acc[1][0]); acc[1][1] = fmaf(a.y, b.y, acc[1][1]);
            acc[1][2] = fmaf(a.y, b.z, acc[1][2]); acc[1][3] = fmaf(a.y, b.w, acc[1][3]);
            acc[2][0] = fmaf(a.z, b.x, acc[2][0]); acc[2][1] = fmaf(a.z, b.y, acc[2][1]);
            acc[2][2] = fmaf(a.z, b.z, acc[2][2]); acc[2][3] = fmaf(a.z, b.w, acc[2][3]);
            acc[3][0] = fmaf(a.w, b.x, acc[3][0]); acc[3][1] = fmaf(a.w, b.y, acc[3][1]);
            acc[3][2] = fmaf(a.w, b.z, acc[3][2]); acc[3][3] = fmaf(a.w, b.w, acc[3][3]);
        }
    }

#pragma unroll
    for (int r = 0; r < 4; ++r) {
        int gi = m0 + tig * 4 + r;
#pragma unroll
        for (int c = 0; c < 4; ++c) {
            int gj = n0 + tjg * 4 + c;
            float v = acc[r][c];
            if (bias) v += bias[gj];
            if (res)  v += res[(size_t)gi * N + gj];
            if (doRelu) v = fmaxf(v, 0.0f);
            C[(size_t)gi * N + gj] = v;
        }
    }
}

// ---------------------------------------------------------------------------
// predX[i][c'] segs (hi, lo, hi) from fp32 pred
// ---------------------------------------------------------------------------
__global__ void __launch_bounds__(256)
predsplit_kernel(const float* __restrict__ pred, __nv_bfloat16* __restrict__ out)
{
    int i = blockIdx.x, c = threadIdx.x;
    float v = pred[i * 256 + c];
    __nv_bfloat16 hi = __float2bfloat16(v);
    __nv_bfloat16 lo = __float2bfloat16(v - __bfloat162float(hi));
    size_t base = (size_t)i * KP;
    out[base + c] = hi;
    out[base + 256 + c] = lo;
    out[base + 512 + c] = hi;
}

// ---------------------------------------------------------------------------
// posX[k][j][c'] segs (hi, hi, lo) from positive[j][c][k] (transpose+split)
// ---------------------------------------------------------------------------
__global__ void __launch_bounds__(256)
possplit_kernel(const float* __restrict__ in, __nv_bfloat16* __restrict__ out)
{
    __shared__ float tile[32][33];
    const int rbase = blockIdx.x * 32;
    const int kbase = blockIdx.y * 32;
    const int tx = threadIdx.x, ty = threadIdx.y;

#pragma unroll
    for (int m = 0; m < 4; ++m)
        tile[ty + m * 8][tx] = in[(size_t)(rbase + ty + m * 8) * 256 + kbase + tx];
    __syncthreads();
#pragma unroll
    for (int m = 0; m < 4; ++m) {
        int k = kbase + ty + m * 8;
        int r = rbase + tx;
        int j = r >> 8, c = r & 255;
        float v = tile[tx][ty + m * 8];
        __nv_bfloat16 hi = __float2bfloat16(v);
        __nv_bfloat16 lo = __float2bfloat16(v - __bfloat162float(hi));
        size_t base = ((size_t)k * BSZ + j) * KP;
        out[base + c] = hi;
        out[base + 256 + c] = hi;
        out[base + 512 + c] = lo;
    }
}

// ---------------------------------------------------------------------------
// HMMA contrast kernel. CTA = (k, 64-row i-tile), full j=512, K'=768.
// 8 warps = 8 j-groups of 64 cols; every warp covers all 64 i rows.
// B fragments ldmatrix'd exactly once per CTA. 128 fp32 acc regs/thread.
// 3-stage cp.async ring (K-chunk 32), one __syncthreads per chunk.
// ---------------------------------------------------------------------------
#define AST      80                      // padded SMEM row stride (bytes)
#define STAGE_SZ (64 * AST + 512 * AST)  // A tile + B tile = 46080
#define OF_B     (64 * AST)              // B offset within a stage
#define CT_SMEM  (3 * STAGE_SZ + 128)

__global__ void __launch_bounds__(256, 1)
contrast_mma(const __nv_bfloat16* __restrict__ predX,
             const __nv_bfloat16* __restrict__ posX,
             float* __restrict__ out)
{
    extern __shared__ char smem[];
    const uint32_t sb = smem_u32(smem);
    const int tid = threadIdx.x;
    const int wid = tid >> 5, lid = tid & 31;
    const int k  = blockIdx.x >> 3;
    const int i0 = (blockIdx.x & 7) << 6;

    // loader indices: 64 rows x 4 16B quads per tile
    const int r = tid >> 2, q = tid & 3;
    const char* Ab = (const char*)(predX + (size_t)i0 * KP);
    const char* Bb = (const char*)(posX + (size_t)k * BSZ * KP);

    float acc[32][4];   // tile t = mi*8 + njp*2 + hb   (mi 0..3, njp 0..3, hb 0..1)
#pragma unroll
    for (int t = 0; t < 32; ++t) {
        acc[t][0] = 0.f; acc[t][1] = 0.f; acc[t][2] = 0.f; acc[t][3] = 0.f;
    }

    auto loadChunk = [&](int n) {
        const uint32_t st = sb + (n % 3) * STAGE_SZ;
        const size_t co = (size_t)n * 64 + q * 16;
        cp16(st + r * AST + q * 16, Ab + (size_t)r * (KP * 2) + co);
#pragma unroll
        for (int it = 0; it < 8; ++it) {
            int row = r + it * 64;
            cp16(st + OF_B + row * AST + q * 16, Bb + (size_t)row * (KP * 2) + co);
        }
        CP_COMMIT();
    };

    // ldmatrix lane addressing
    const uint32_t lquad = (uint32_t)(lid >> 4) * 16;
    const uint32_t lrow  = (uint32_t)(lid & 15);
    const uint32_t lA = lrow * AST + lquad;                       // + mi*16*AST
    const uint32_t lB = (uint32_t)(wid * 64 + lrow) * AST + lquad; // + njp*16*AST

    loadChunk(0);
    loadChunk(1);

#pragma unroll 1
    for (int n = 0; n < 24; ++n) {
        CP_WAIT(1);
        __syncthreads();
        if (n + 2 < 24) loadChunk(n + 2);

        const uint32_t st = sb + (n % 3) * STAGE_SZ;
        const uint32_t at = st + lA;
        const uint32_t bt = st + OF_B + lB;
#pragma unroll
        for (int ks = 0; ks < 2; ++ks) {
            uint32_t a[4][4];
#pragma unroll
            for (int mi = 0; mi < 4; ++mi)
                ldmx4(a[mi][0], a[mi][1], a[mi][2], a[mi][3],
                      at + mi * 16 * AST + ks * 32);
#pragma unroll
            for (int njp = 0; njp < 4; ++njp) {
                uint32_t b0, b1, b2, b3;
                ldmx4(b0, b1, b2, b3, bt + njp * 16 * AST + ks * 32);
#pragma unroll
                for (int mi = 0; mi < 4; ++mi) {
                    mma16816(acc[mi * 8 + njp * 2 + 0],
                             a[mi][0], a[mi][1], a[mi][2], a[mi][3], b0, b2);
                    mma16816(acc[mi * 8 + njp * 2 + 1],
                             a[mi][0], a[mi][1], a[mi][2], a[mi][3], b1, b3);
                }
            }
        }
    }

    // ---- fused row-max: every warp covers all 64 i rows, distinct j ----
    float mx0[4], mx1[4];
#pragma unroll
    for (int mi = 0; mi < 4; ++mi) {
        mx0[mi] = -3.402823466e38f;
        mx1[mi] = -3.402823466e38f;
#pragma unroll
        for (int nj = 0; nj < 8; ++nj) {
            const float* c = acc[mi * 8 + nj];
            mx0[mi] = fmaxf(mx0[mi], fmaxf(c[0], c[1]));
            mx1[mi] = fmaxf(mx1[mi], fmaxf(c[2], c[3]));
        }
        mx0[mi] = fmaxf(mx0[mi], __shfl_xor_sync(0xffffffffu, mx0[mi], 1));
        mx0[mi] = fmaxf(mx0[mi], __shfl_xor_sync(0xffffffffu, mx0[mi], 2));
        mx1[mi] = fmaxf(mx1[mi], __shfl_xor_sync(0xffffffffu, mx1[mi], 1));
        mx1[mi] = fmaxf(mx1[mi], __shfl_xor_sync(0xffffffffu, mx1[mi], 2));
    }

    __syncthreads();                       // mainloop SMEM reads done
    float* rmax = (float*)smem;            // [8 warps][64 rows]
    const int tr = lid >> 2;               // 0..7
    if ((lid & 3) == 0) {
#pragma unroll
        for (int mi = 0; mi < 4; ++mi) {
            rmax[wid * 64 + mi * 16 + tr]     = mx0[mi];
            rmax[wid * 64 + mi * 16 + 8 + tr] = mx1[mi];
        }
    }
    __syncthreads();

    float m0[4], m1[4];
#pragma unroll
    for (int mi = 0; mi < 4; ++mi) {
        float a0 = -3.402823466e38f, a1 = -3.402823466e38f;
#pragma unroll
        for (int w = 0; w < 8; ++w) {
            a0 = fmaxf(a0, rmax[w * 64 + mi * 16 + tr]);
            a1 = fmaxf(a1, rmax[w * 64 + mi * 16 + 8 + tr]);
        }
        m0[mi] = a0; m1[mi] = a1;
    }

    // ---- subtract + store (warp's j block = wid*64) ----
    const size_t obase = ((size_t)k * BSZ + i0) * BSZ + wid * 64 + (lid & 3) * 2;
#pragma unroll
    for (int mi = 0; mi < 4; ++mi) {
        float* o0 = out + obase + (size_t)(mi * 16 + tr) * BSZ;
        float* o1 = o0 + (size_t)8 * BSZ;
#pragma unroll
        for (int nj = 0; nj < 8; ++nj) {
            const float* c = acc[mi * 8 + nj];
            *(float2*)(o0 + nj * 8) = make_float2(c[0] - m0[mi], c[1] - m0[mi]);
            *(float2*)(o1 + nj * 8) = make_float2(c[2] - m1[mi], c[3] - m1[mi]);
        }
    }
}

// ---------------------------------------------------------------------------
// Launch
// ---------------------------------------------------------------------------
extern "C" void kernel_launch(void* const* d_in, const int* in_sizes, int n_in,
                              void* d_out, int out_size)
{
    const float* anchor   = (const float*)d_in[0];
    const float* positive = (const float*)d_in[1];
    const float* W1       = (const float*)d_in[2];
    const float* b1       = (const float*)d_in[3];
    const float* W2       = (const float*)d_in[4];
    const float* b2       = (const float*)d_in[5];
    const float* Wc       = (const float*)d_in[6];
    float* out            = (float*)d_out;

    float *hp, *ap, *pp;
    __nv_bfloat16 *px, *qx;
    cudaGetSymbolAddress((void**)&hp, g_h);
    cudaGetSymbolAddress((void**)&ap, g_a);
    cudaGetSymbolAddress((void**)&pp, g_pred);
    cudaGetSymbolAddress((void**)&qx, g_predX);
    cudaGetSymbolAddress((void**)&px, g_posX);

    cudaFuncSetAttribute(contrast_mma,
                         cudaFuncAttributeMaxDynamicSharedMemorySize, CT_SMEM);

    // MLP chain (fp32)
    gemm_tile<<<dim3(HIDDEN / 64, BSZ / 64), 256>>>(
        anchor, W1, b1, nullptr, hp, BSZ, HIDDEN, LATENT, 1);
    gemm_tile<<<dim3(LATENT / 64, BSZ / 64), 256>>>(
        hp, W2, b2, anchor, ap, BSZ, LATENT, HIDDEN, 0);
    gemm_tile<<<dim3(LATENT / 64, BSZ / 64), 256>>>(
        ap, Wc, nullptr, nullptr, pp, BSZ, LATENT, LATENT, 0);

    // hi/lo split prep
    predsplit_kernel<<<BSZ, 256>>>(pp, qx);
    possplit_kernel<<<dim3((BSZ * 256) / 32, HW / 32), dim3(32, 8)>>>(positive, px);

    // HMMA contrast GEMM + fused rowmax
    contrast_mma<<<HW * 8, 256, CT_SMEM>>>(qx, px, out);
}